// round 6
// baseline (speedup 1.0000x reference)
#include <cuda_runtime.h>
#include <cuda_bf16.h>
#include <math.h>
#include <stdint.h>

#define B_  2
#define T_  2048
#define D_  1024
#define H_  16
#define DH_ 64
#define NTOK (B_*T_)          // 4096
#define K3  3072

// ---------------- scratch (device globals; no allocation) ----------------
__device__ __align__(256) float g_integral[(size_t)NTOK * D_];
__device__ float g_params[(size_t)NTOK * 12];
__device__ __align__(256) __nv_bfloat16 g_abc_hi[(size_t)3 * NTOK * K3];
__device__ __align__(256) __nv_bfloat16 g_abc_lo[(size_t)3 * NTOK * K3];
__device__ __align__(256) __nv_bfloat16 g_w_hi[(size_t)3 * 1024 * K3];
__device__ __align__(256) __nv_bfloat16 g_w_lo[(size_t)3 * 1024 * K3];
__device__ __align__(256) __nv_bfloat16 g_ow_hi[(size_t)1024 * 1024];
__device__ __align__(256) __nv_bfloat16 g_ow_lo[(size_t)1024 * 1024];
__device__ __align__(256) float g_q[(size_t)NTOK * D_];
__device__ __align__(256) float g_k[(size_t)NTOK * D_];
__device__ __align__(256) float g_v[(size_t)NTOK * D_];
__device__ __align__(256) __nv_bfloat16 g_att_hi[(size_t)NTOK * D_];
__device__ __align__(256) __nv_bfloat16 g_att_lo[(size_t)NTOK * D_];

// ============================ PTX helpers (sm_100-baseline safe) ============================
__device__ __forceinline__ uint32_t s2u(const void* p) {
    uint32_t a;
    asm("{ .reg .u64 t; cvta.to.shared.u64 t, %1; cvt.u32.u64 %0, t; }" : "=r"(a) : "l"(p));
    return a;
}
__device__ __forceinline__ void cp_async16(uint32_t dst, const void* src) {
    asm volatile("cp.async.cg.shared.global [%0], [%1], 16;" :: "r"(dst), "l"(src));
}
__device__ __forceinline__ void cp_commit() {
    asm volatile("cp.async.commit_group;" ::: "memory");
}
__device__ __forceinline__ void cp_wait2() {
    asm volatile("cp.async.wait_group 2;" ::: "memory");
}
__device__ __forceinline__ void ldsm_x4(uint32_t* r, uint32_t addr) {
    asm volatile("ldmatrix.sync.aligned.m8n8.x4.shared.b16 {%0,%1,%2,%3}, [%4];"
        : "=r"(r[0]), "=r"(r[1]), "=r"(r[2]), "=r"(r[3]) : "r"(addr));
}
__device__ __forceinline__ void mma_bf16(float* d, const uint32_t* a, const uint32_t* b) {
    asm volatile(
        "mma.sync.aligned.m16n8k16.row.col.f32.bf16.bf16.f32 "
        "{%0,%1,%2,%3}, {%4,%5,%6,%7}, {%8,%9}, {%0,%1,%2,%3};"
        : "+f"(d[0]), "+f"(d[1]), "+f"(d[2]), "+f"(d[3])
        : "r"(a[0]), "r"(a[1]), "r"(a[2]), "r"(a[3]), "r"(b[0]), "r"(b[1]));
}

// ============================ misc kernels ============================
__global__ void token_stats_kernel(const float* __restrict__ x,
                                   const float* __restrict__ gate_w,
                                   const float* __restrict__ gate_b,
                                   const float* __restrict__ kick_w,
                                   const float* __restrict__ kick_b)
{
    int r = blockIdx.x;
    int t = r % T_;
    const float* xt = x + (size_t)r * D_;
    int tid = threadIdx.x;

    float acc[15];
#pragma unroll
    for (int v = 0; v < 15; v++) acc[v] = 0.f;

    for (int d = tid; d < D_; d += 128) {
        float xv = xt[d];
        float pv = (t > 0) ? xt[d - D_] : 0.f;
        acc[0] = fmaf(xv, xv, acc[0]);
        acc[1] = fmaf(xv, pv, acc[1]);
        acc[2] = fmaf(pv, pv, acc[2]);
        acc[3] = fmaf(xv, kick_w[0 * D_ + d], acc[3]);
        acc[4] = fmaf(xv, kick_w[1 * D_ + d], acc[4]);
        acc[5] = fmaf(xv, kick_w[2 * D_ + d], acc[5]);
#pragma unroll
        for (int j = 0; j < 9; j++)
            acc[6 + j] = fmaf(xv, gate_w[j * D_ + d], acc[6 + j]);
    }
#pragma unroll
    for (int v = 0; v < 15; v++)
#pragma unroll
        for (int off = 16; off; off >>= 1)
            acc[v] += __shfl_down_sync(0xffffffffu, acc[v], off);

    __shared__ float red[15][4];
    int w = tid >> 5, l = tid & 31;
    if (l == 0)
#pragma unroll
        for (int v = 0; v < 15; v++) red[v][w] = acc[v];
    __syncthreads();

    if (tid == 0) {
        float s[15];
#pragma unroll
        for (int v = 0; v < 15; v++)
            s[v] = red[v][0] + red[v][1] + red[v][2] + red[v][3];
        float nt = fmaxf(sqrtf(s[0]), 1e-12f);
        float np = fmaxf(sqrtf(s[2]), 1e-12f);
        float cosv = (t > 0) ? s[1] / (nt * np) : 0.f;
        float stag = (cosv > 0.95f) ? 1.f : 0.f;
        float* out = g_params + (size_t)r * 12;
#pragma unroll
        for (int p = 0; p < 3; p++) {
            float ks = 1.f / (1.f + expf(-(s[3 + p] + kick_b[p])));
            float l0 = s[6 + p * 3 + 0] + gate_b[p * 3 + 0];
            float l1 = s[6 + p * 3 + 1] + gate_b[p * 3 + 1];
            float l2 = s[6 + p * 3 + 2] + gate_b[p * 3 + 2];
            float m = fmaxf(l0, fmaxf(l1, l2));
            float e0 = expf(l0 - m), e1 = expf(l1 - m), e2 = expf(l2 - m);
            float inv = 1.f / (e0 + e1 + e2);
            float g0 = fminf(e0 * inv, 0.6f);
            float g1 = fminf(e1 * inv, 0.6f);
            float g2 = fminf(e2 * inv, 0.6f);
            g1 = fmaxf(g1, 0.25f);
            float gi = 1.f / (g0 + g1 + g2);
            out[p * 4 + 0] = g0 * gi;
            out[p * 4 + 1] = g1 * gi;
            out[p * 4 + 2] = g2 * gi;
            out[p * 4 + 3] = stag * ks;
        }
    }
}

__global__ void ema_kernel(const float* __restrict__ x)
{
    int c = blockIdx.x * blockDim.x + threadIdx.x;
    if (c >= B_ * D_) return;
    int b = c / D_, d = c % D_;
    const float* xp = x + (size_t)b * T_ * D_ + d;
    float* ip = g_integral + (size_t)b * T_ * D_ + d;
    float acc = xp[0];
    ip[0] = acc;
#pragma unroll 8
    for (int t = 1; t < T_; t++) {
        acc = fmaf(0.95f, acc, 0.05f * xp[(size_t)t * D_]);
        ip[(size_t)t * D_] = acc;
    }
}

// pack two fp32 into hi/lo bf16 pairs and store as 4B each
__device__ __forceinline__ void split_store2(__nv_bfloat16* hi, __nv_bfloat16* lo,
                                             size_t idx, float v0, float v1) {
    __nv_bfloat16 h0 = __float2bfloat16(v0);
    __nv_bfloat16 h1 = __float2bfloat16(v1);
    __nv_bfloat16 l0 = __float2bfloat16(v0 - __bfloat162float(h0));
    __nv_bfloat16 l1 = __float2bfloat16(v1 - __bfloat162float(h1));
    __nv_bfloat162 hp; hp.x = h0; hp.y = h1;
    __nv_bfloat162 lp; lp.x = l0; lp.y = l1;
    *(__nv_bfloat162*)(hi + idx) = hp;
    *(__nv_bfloat162*)(lo + idx) = lp;
}

__global__ void build_abc_kernel(const float* __restrict__ x,
                                 const float* __restrict__ kick_v)
{
    int r = blockIdx.x;
    int p = blockIdx.y;
    int t = r % T_;
    const float* par = g_params + (size_t)r * 12 + p * 4;
    float g0 = par[0], g1 = par[1], g2 = par[2], km = par[3];
    size_t base = ((size_t)p * NTOK + r) * K3;
    const float* xt = x + (size_t)r * D_;
    const float* integ = g_integral + (size_t)r * D_;
    for (int d2 = threadIdx.x; d2 < D_ / 2; d2 += blockDim.x) {
        int d = d2 * 2;
        float2 xv = *(const float2*)(xt + d);
        float2 iv = *(const float2*)(integ + d);
        float der0, der1;
        if (t > 0) {
            float2 pv = *(const float2*)(xt + d - D_);
            der0 = xv.x - pv.x; der1 = xv.y - pv.y;
        } else { der0 = 0.f; der1 = 0.f; }
        float2 kv = *(const float2*)(kick_v + p * D_ + d);
        der0 = fmaf(km, kv.x, der0);
        der1 = fmaf(km, kv.y, der1);
        split_store2(g_abc_hi, g_abc_lo, base + d,          g0 * xv.x, g0 * xv.y);
        split_store2(g_abc_hi, g_abc_lo, base + D_ + d,     g1 * iv.x, g1 * iv.y);
        split_store2(g_abc_hi, g_abc_lo, base + 2 * D_ + d, g2 * der0, g2 * der1);
    }
}

__global__ void conv_w_kernel(const float* __restrict__ Wp,
                              const float* __restrict__ Wi,
                              const float* __restrict__ Wd)
{
    size_t i2 = (size_t)blockIdx.x * blockDim.x + threadIdx.x;
    if (i2 >= (size_t)3 * 1024 * K3 / 2) return;
    size_t i = i2 * 2;
    int k = (int)(i % K3);
    size_t pn = i / K3;
    int sel = k >> 10;
    const float* src = (sel == 0) ? Wp : (sel == 1) ? Wi : Wd;
    float2 v = *(const float2*)(src + pn * 1024 + (k & 1023));
    split_store2(g_w_hi, g_w_lo, i, v.x, v.y);
}

__global__ void conv_ow_kernel(const float* __restrict__ ow)
{
    size_t i2 = (size_t)blockIdx.x * blockDim.x + threadIdx.x;
    if (i2 >= (size_t)1024 * 1024 / 2) return;
    size_t i = i2 * 2;
    float2 v = *(const float2*)(ow + i);
    split_store2(g_ow_hi, g_ow_lo, i, v.x, v.y);
}

// ============================ bf16x3 mma.sync GEMM v4 ============================
// C[M x 1024] = Ah*Bh^T + Al*Bh^T + Ah*Bl^T   (A [m][k], B=W [n][k], both k-contiguous)
// CTA tile 128(M) x 256(N), 8 warps 2x4 (warp tile 64x64), KT=64,
// 4-stage cp.async + register double-buffered fragments.
#define KT      64
#define GSTG    4
#define ROWB    144                    // 128B data + 16B skew: conflict-free ldmatrix
#define ATILE_SZ (128 * ROWB)          // 18432
#define BTILE_SZ (256 * ROWB)          // 36864
#define STAGE_SZ (ATILE_SZ + BTILE_SZ) // 55296
#define GEMM_SMEM (GSTG * STAGE_SZ)    // 221184

__device__ __forceinline__ void gemm_issue(
    const __nv_bfloat16* As, const __nv_bfloat16* Bs, int K,
    uint32_t sb, int tid, int stage, int kk, int m0, int brow0)
{
    uint32_t st = sb + stage * STAGE_SZ;
#pragma unroll
    for (int j = 0; j < 12; j++) {
        int i = tid + j * 256;             // 0..3071
        bool isB = (i >= 1024);
        int idx = isB ? i - 1024 : i;
        int row = idx >> 3, c = idx & 7;   // 8 x 16B = 128B per row
        const __nv_bfloat16* src = (isB ? Bs + (size_t)(brow0 + row) * K
                                        : As + (size_t)(m0 + row) * K) + kk + c * 8;
        uint32_t dst = st + (isB ? ATILE_SZ : 0) + row * ROWB + c * 16;
        cp_async16(dst, src);
    }
    cp_commit();
}

__global__ void __launch_bounds__(256, 1)
gemm_bf16x3(const __nv_bfloat16* __restrict__ Ah, const __nv_bfloat16* __restrict__ Al,
            const __nv_bfloat16* __restrict__ Bh, const __nv_bfloat16* __restrict__ Bl,
            float* c0, float* c1, float* c2, int kpt, int K)
{
    extern __shared__ __align__(256) char smem[];
    uint32_t sb = s2u(smem);
    int tid = threadIdx.x, lane = tid & 31, wid = tid >> 5;
    int wm = wid >> 2, wn = wid & 3;       // 2 x 4 warp grid, warp tile 64x64
    int by = blockIdx.y, bx = blockIdx.x;
    int proj = by >> 5;
    int m0 = by * 128;
    int brow0 = proj * 1024 + bx * 256;
    int NC = 3 * kpt;

    float d[4][8][4];
#pragma unroll
    for (int i = 0; i < 4; i++)
#pragma unroll
        for (int j = 0; j < 8; j++)
#pragma unroll
            for (int q = 0; q < 4; q++) d[i][j][q] = 0.f;

    uint32_t a_off = (uint32_t)((wm * 64 + (lane & 15)) * ROWB + (lane >> 4) * 16);
    uint32_t b_off = (uint32_t)(ATILE_SZ
                     + (wn * 64 + ((lane >> 4) << 3) + (lane & 7)) * ROWB
                     + ((lane >> 3) & 1) * 16);

    // producer counters (no division in the loop)
    int pterm = 0, pkc = 0;
    const __nv_bfloat16* pA = Ah;
    const __nv_bfloat16* pB = Bh;

    // prologue: 3 chunks (stages 0,1,2)
#pragma unroll
    for (int pr = 0; pr < 3; pr++) {
        gemm_issue(pA, pB, K, sb, tid, pr, pkc * KT, m0, brow0);
        if (++pkc == kpt) {
            pkc = 0; pterm++;
            pA = (pterm == 1) ? Al : Ah;
            pB = (pterm == 2) ? Bl : Bh;
        }
    }
    int pstage = 3;

    uint32_t a[2][4][4], b[2][4][4];

    for (int kc = 0; kc < NC; kc++) {
        cp_wait2();
        __syncthreads();
        // issue chunk kc+3 into stage (kc+3)&3 == (kc-1)&3, whose readers
        // were fenced by this iteration's entry sync — overlap with compute below
        if (pterm < 3) {
            gemm_issue(pA, pB, K, sb, tid, pstage, pkc * KT, m0, brow0);
            if (++pkc == kpt) {
                pkc = 0; pterm++;
                pA = (pterm == 1) ? Al : Ah;
                pB = (pterm == 2) ? Bl : Bh;
            }
            if (++pstage == GSTG) pstage = 0;
        } else {
            cp_commit();   // keep group accounting uniform
        }

        uint32_t st = sb + (kc & (GSTG - 1)) * STAGE_SZ;
        // prefetch ks=0 fragments
#pragma unroll
        for (int mb = 0; mb < 4; mb++)
            ldsm_x4(a[0][mb], st + a_off + mb * 16 * ROWB);
#pragma unroll
        for (int nb = 0; nb < 4; nb++)
            ldsm_x4(b[0][nb], st + b_off + nb * 16 * ROWB);

#pragma unroll
        for (int ks = 0; ks < 4; ks++) {
            int cur = ks & 1, nxt = cur ^ 1;
            if (ks < 3) {
                uint32_t a0 = st + a_off + (ks + 1) * 32;
                uint32_t ab = st + b_off + (ks + 1) * 32;
#pragma unroll
                for (int mb = 0; mb < 4; mb++)
                    ldsm_x4(a[nxt][mb], a0 + mb * 16 * ROWB);
#pragma unroll
                for (int nb = 0; nb < 4; nb++)
                    ldsm_x4(b[nxt][nb], ab + nb * 16 * ROWB);
            }
#pragma unroll
            for (int mb = 0; mb < 4; mb++)
#pragma unroll
                for (int nb = 0; nb < 4; nb++) {
                    mma_bf16(d[mb][2 * nb],     a[cur][mb], b[cur][nb]);
                    mma_bf16(d[mb][2 * nb + 1], a[cur][mb], b[cur][nb] + 2);
                }
        }
    }

    // epilogue
    float* C = (proj == 0) ? c0 : (proj == 1) ? c1 : c2;
    int g = lane >> 2, q = lane & 3;
    int rb = (by & 31) * 128 + wm * 64;
    int cb = bx * 256 + wn * 64;
#pragma unroll
    for (int mb = 0; mb < 4; mb++) {
#pragma unroll
        for (int nt = 0; nt < 8; nt++) {
            float* cp = C + (size_t)(rb + mb * 16 + g) * 1024 + cb + nt * 8 + q * 2;
            *(float2*)cp = make_float2(d[mb][nt][0], d[mb][nt][1]);
            *(float2*)(cp + 8 * 1024) = make_float2(d[mb][nt][2], d[mb][nt][3]);
        }
    }
}

// ============================ sparse attention ============================
template<int AA>
__global__ void attn_kernel(const int* __restrict__ positions)
{
    int wid = (blockIdx.x * blockDim.x + threadIdx.x) >> 5;
    int lane = threadIdx.x & 31;
    if (wid >= B_ * H_ * T_) return;
    int t = wid % T_;
    int h = (wid / T_) % H_;
    int b = wid / (T_ * H_);

    const float* qp = g_q + ((size_t)b * T_ + t) * D_ + h * DH_;
    int d0 = lane * 2;
    float q0 = qp[d0], q1 = qp[d0 + 1];

    int nv = 1 + min(3, t);
    if (t >= 4) nv += (31 - __clz((unsigned)t)) - 1;

    float sc[AA];
    int ps[AA];
    float mx = -1e30f;
#pragma unroll
    for (int a = 0; a < AA; a++) {
        int pos = positions[t * AA + a];
        ps[a] = pos;
        const float* kp = g_k + ((size_t)b * T_ + pos) * D_ + h * DH_;
        float s = fmaf(q0, kp[d0], q1 * kp[d0 + 1]);
#pragma unroll
        for (int o = 16; o; o >>= 1) s += __shfl_xor_sync(0xffffffffu, s, o);
        s = (a < nv) ? s * 0.125f : -1e30f;
        sc[a] = s;
        mx = fmaxf(mx, s);
    }
    float sum = 0.f;
#pragma unroll
    for (int a = 0; a < AA; a++) { sc[a] = expf(sc[a] - mx); sum += sc[a]; }
    float inv = 1.f / sum;
    float o0 = 0.f, o1 = 0.f;
#pragma unroll
    for (int a = 0; a < AA; a++) {
        const float* vp = g_v + ((size_t)b * T_ + ps[a]) * D_ + h * DH_;
        float wgt = sc[a] * inv;
        o0 = fmaf(wgt, vp[d0], o0);
        o1 = fmaf(wgt, vp[d0 + 1], o1);
    }
    size_t oi = ((size_t)b * T_ + t) * D_ + h * DH_ + d0;
    split_store2(g_att_hi, g_att_lo, oi, o0, o1);
}

__global__ void attn_kernel_dyn(const int* __restrict__ positions, int A)
{
    int wid = (blockIdx.x * blockDim.x + threadIdx.x) >> 5;
    int lane = threadIdx.x & 31;
    if (wid >= B_ * H_ * T_) return;
    int t = wid % T_;
    int h = (wid / T_) % H_;
    int b = wid / (T_ * H_);
    const float* qp = g_q + ((size_t)b * T_ + t) * D_ + h * DH_;
    int d0 = lane * 2;
    float q0 = qp[d0], q1 = qp[d0 + 1];
    int nv = 1 + min(3, t);
    if (t >= 4) nv += (31 - __clz((unsigned)t)) - 1;
    float sc[32]; int ps[32];
    float mx = -1e30f;
    for (int a = 0; a < A; a++) {
        int pos = positions[t * A + a];
        ps[a] = pos;
        const float* kp = g_k + ((size_t)b * T_ + pos) * D_ + h * DH_;
        float s = fmaf(q0, kp[d0], q1 * kp[d0 + 1]);
        for (int o = 16; o; o >>= 1) s += __shfl_xor_sync(0xffffffffu, s, o);
        s = (a < nv) ? s * 0.125f : -1e30f;
        sc[a] = s; mx = fmaxf(mx, s);
    }
    float sum = 0.f;
    for (int a = 0; a < A; a++) { sc[a] = expf(sc[a] - mx); sum += sc[a]; }
    float inv = 1.f / sum;
    float o0 = 0.f, o1 = 0.f;
    for (int a = 0; a < A; a++) {
        const float* vp = g_v + ((size_t)b * T_ + ps[a]) * D_ + h * DH_;
        float wgt = sc[a] * inv;
        o0 = fmaf(wgt, vp[d0], o0);
        o1 = fmaf(wgt, vp[d0 + 1], o1);
    }
    size_t oi = ((size_t)b * T_ + t) * D_ + h * DH_ + d0;
    split_store2(g_att_hi, g_att_lo, oi, o0, o1);
}

// ============================ launcher ============================
extern "C" void kernel_launch(void* const* d_in, const int* in_sizes, int n_in,
                              void* d_out, int out_size)
{
    const float* x       = (const float*)d_in[0];
    const float* qkv_Wp  = (const float*)d_in[1];
    const float* qkv_Wi  = (const float*)d_in[2];
    const float* qkv_Wd  = (const float*)d_in[3];
    const float* gate_w  = (const float*)d_in[4];
    const float* gate_b  = (const float*)d_in[5];
    const float* kick_v  = (const float*)d_in[6];
    const float* kick_w  = (const float*)d_in[7];
    const float* kick_b  = (const float*)d_in[8];
    const float* o_w     = (const float*)d_in[9];
    const int*   positions = (const int*)d_in[10];
    int A = in_sizes[10] / T_;

    float* out = (float*)d_out;

    void *p_abc_hi, *p_abc_lo, *p_w_hi, *p_w_lo, *p_ow_hi, *p_ow_lo;
    void *p_q, *p_k, *p_v, *p_att_hi, *p_att_lo;
    cudaGetSymbolAddress(&p_abc_hi, g_abc_hi);
    cudaGetSymbolAddress(&p_abc_lo, g_abc_lo);
    cudaGetSymbolAddress(&p_w_hi, g_w_hi);
    cudaGetSymbolAddress(&p_w_lo, g_w_lo);
    cudaGetSymbolAddress(&p_ow_hi, g_ow_hi);
    cudaGetSymbolAddress(&p_ow_lo, g_ow_lo);
    cudaGetSymbolAddress(&p_q, g_q);
    cudaGetSymbolAddress(&p_k, g_k);
    cudaGetSymbolAddress(&p_v, g_v);
    cudaGetSymbolAddress(&p_att_hi, g_att_hi);
    cudaGetSymbolAddress(&p_att_lo, g_att_lo);

    cudaFuncSetAttribute(gemm_bf16x3, cudaFuncAttributeMaxDynamicSharedMemorySize, GEMM_SMEM);

    // 1. per-token gates / kick / stagnation
    token_stats_kernel<<<NTOK, 128>>>(x, gate_w, gate_b, kick_w, kick_b);
    // 2. EMA integral
    ema_kernel<<<(B_ * D_ + 255) / 256, 256>>>(x);
    // 3. weight hi/lo conversion (vectorized x2)
    conv_w_kernel<<<(3 * 1024 * K3 / 2 + 255) / 256, 256>>>(qkv_Wp, qkv_Wi, qkv_Wd);
    conv_ow_kernel<<<(1024 * 1024 / 2 + 255) / 256, 256>>>(o_w);
    // 4. gated GEMM inputs (hi/lo bf16)
    dim3 gb(NTOK, 3);
    build_abc_kernel<<<gb, 256>>>(x, kick_v);
    // 5. projection GEMMs: grid (1024/256, 3*4096/128) = (4, 96)
    dim3 pgrid(1024 / 256, 3 * (NTOK / 128));
    gemm_bf16x3<<<pgrid, 256, GEMM_SMEM>>>(
        (const __nv_bfloat16*)p_abc_hi, (const __nv_bfloat16*)p_abc_lo,
        (const __nv_bfloat16*)p_w_hi, (const __nv_bfloat16*)p_w_lo,
        (float*)p_q, (float*)p_k, (float*)p_v, K3 / KT, K3);
    // 6. sparse dilated attention
    int nwarps = B_ * H_ * T_;
    int nblocks = nwarps / 4;
    if (A == 15)
        attn_kernel<15><<<nblocks, 128>>>(positions);
    else
        attn_kernel_dyn<<<nblocks, 128>>>(positions, A);
    // 7. output projection: grid (4, 32)
    dim3 ogrid(1024 / 256, NTOK / 128);
    gemm_bf16x3<<<ogrid, 256, GEMM_SMEM>>>(
        (const __nv_bfloat16*)p_att_hi, (const __nv_bfloat16*)p_att_lo,
        (const __nv_bfloat16*)p_ow_hi, (const __nv_bfloat16*)p_ow_lo,
        out, out, out, D_ / KT, D_);
}

// round 7
// speedup vs baseline: 1.0469x; 1.0469x over previous
#include <cuda_runtime.h>
#include <cuda_bf16.h>
#include <math.h>
#include <stdint.h>

#define B_  2
#define T_  2048
#define D_  1024
#define H_  16
#define DH_ 64
#define NTOK (B_*T_)          // 4096
#define K3  3072

// ---------------- scratch (device globals; no allocation) ----------------
__device__ __align__(256) float g_integral[(size_t)NTOK * D_];
__device__ float g_params[(size_t)NTOK * 12];
__device__ __align__(256) __nv_bfloat16 g_abc_hi[(size_t)3 * NTOK * K3];
__device__ __align__(256) __nv_bfloat16 g_abc_lo[(size_t)3 * NTOK * K3];
__device__ __align__(256) __nv_bfloat16 g_w_hi[(size_t)3 * 1024 * K3];
__device__ __align__(256) __nv_bfloat16 g_w_lo[(size_t)3 * 1024 * K3];
__device__ __align__(256) __nv_bfloat16 g_ow_hi[(size_t)1024 * 1024];
__device__ __align__(256) __nv_bfloat16 g_ow_lo[(size_t)1024 * 1024];
__device__ __align__(256) float g_q[(size_t)NTOK * D_];
__device__ __align__(256) float g_k[(size_t)NTOK * D_];
__device__ __align__(256) float g_v[(size_t)NTOK * D_];
__device__ __align__(256) __nv_bfloat16 g_att_hi[(size_t)NTOK * D_];
__device__ __align__(256) __nv_bfloat16 g_att_lo[(size_t)NTOK * D_];

// ============================ PTX helpers (sm_100-baseline safe) ============================
__device__ __forceinline__ uint32_t s2u(const void* p) {
    uint32_t a;
    asm("{ .reg .u64 t; cvta.to.shared.u64 t, %1; cvt.u32.u64 %0, t; }" : "=r"(a) : "l"(p));
    return a;
}
__device__ __forceinline__ void cp_async16(uint32_t dst, const void* src) {
    asm volatile("cp.async.cg.shared.global [%0], [%1], 16;" :: "r"(dst), "l"(src));
}
__device__ __forceinline__ void cp_commit() {
    asm volatile("cp.async.commit_group;" ::: "memory");
}
__device__ __forceinline__ void cp_wait1() {
    asm volatile("cp.async.wait_group 1;" ::: "memory");
}
__device__ __forceinline__ void ldsm_x4(uint32_t* r, uint32_t addr) {
    asm volatile("ldmatrix.sync.aligned.m8n8.x4.shared.b16 {%0,%1,%2,%3}, [%4];"
        : "=r"(r[0]), "=r"(r[1]), "=r"(r[2]), "=r"(r[3]) : "r"(addr));
}
__device__ __forceinline__ void mma_bf16(float* d, const uint32_t* a, const uint32_t* b) {
    asm volatile(
        "mma.sync.aligned.m16n8k16.row.col.f32.bf16.bf16.f32 "
        "{%0,%1,%2,%3}, {%4,%5,%6,%7}, {%8,%9}, {%0,%1,%2,%3};"
        : "+f"(d[0]), "+f"(d[1]), "+f"(d[2]), "+f"(d[3])
        : "r"(a[0]), "r"(a[1]), "r"(a[2]), "r"(a[3]), "r"(b[0]), "r"(b[1]));
}

// ============================ misc kernels ============================
__global__ void token_stats_kernel(const float* __restrict__ x,
                                   const float* __restrict__ gate_w,
                                   const float* __restrict__ gate_b,
                                   const float* __restrict__ kick_w,
                                   const float* __restrict__ kick_b)
{
    int r = blockIdx.x;
    int t = r % T_;
    const float* xt = x + (size_t)r * D_;
    int tid = threadIdx.x;

    float acc[15];
#pragma unroll
    for (int v = 0; v < 15; v++) acc[v] = 0.f;

    for (int d = tid; d < D_; d += 128) {
        float xv = xt[d];
        float pv = (t > 0) ? xt[d - D_] : 0.f;
        acc[0] = fmaf(xv, xv, acc[0]);
        acc[1] = fmaf(xv, pv, acc[1]);
        acc[2] = fmaf(pv, pv, acc[2]);
        acc[3] = fmaf(xv, kick_w[0 * D_ + d], acc[3]);
        acc[4] = fmaf(xv, kick_w[1 * D_ + d], acc[4]);
        acc[5] = fmaf(xv, kick_w[2 * D_ + d], acc[5]);
#pragma unroll
        for (int j = 0; j < 9; j++)
            acc[6 + j] = fmaf(xv, gate_w[j * D_ + d], acc[6 + j]);
    }
#pragma unroll
    for (int v = 0; v < 15; v++)
#pragma unroll
        for (int off = 16; off; off >>= 1)
            acc[v] += __shfl_down_sync(0xffffffffu, acc[v], off);

    __shared__ float red[15][4];
    int w = tid >> 5, l = tid & 31;
    if (l == 0)
#pragma unroll
        for (int v = 0; v < 15; v++) red[v][w] = acc[v];
    __syncthreads();

    if (tid == 0) {
        float s[15];
#pragma unroll
        for (int v = 0; v < 15; v++)
            s[v] = red[v][0] + red[v][1] + red[v][2] + red[v][3];
        float nt = fmaxf(sqrtf(s[0]), 1e-12f);
        float np = fmaxf(sqrtf(s[2]), 1e-12f);
        float cosv = (t > 0) ? s[1] / (nt * np) : 0.f;
        float stag = (cosv > 0.95f) ? 1.f : 0.f;
        float* out = g_params + (size_t)r * 12;
#pragma unroll
        for (int p = 0; p < 3; p++) {
            float ks = 1.f / (1.f + expf(-(s[3 + p] + kick_b[p])));
            float l0 = s[6 + p * 3 + 0] + gate_b[p * 3 + 0];
            float l1 = s[6 + p * 3 + 1] + gate_b[p * 3 + 1];
            float l2 = s[6 + p * 3 + 2] + gate_b[p * 3 + 2];
            float m = fmaxf(l0, fmaxf(l1, l2));
            float e0 = expf(l0 - m), e1 = expf(l1 - m), e2 = expf(l2 - m);
            float inv = 1.f / (e0 + e1 + e2);
            float g0 = fminf(e0 * inv, 0.6f);
            float g1 = fminf(e1 * inv, 0.6f);
            float g2 = fminf(e2 * inv, 0.6f);
            g1 = fmaxf(g1, 0.25f);
            float gi = 1.f / (g0 + g1 + g2);
            out[p * 4 + 0] = g0 * gi;
            out[p * 4 + 1] = g1 * gi;
            out[p * 4 + 2] = g2 * gi;
            out[p * 4 + 3] = stag * ks;
        }
    }
}

__global__ void ema_kernel(const float* __restrict__ x)
{
    int c = blockIdx.x * blockDim.x + threadIdx.x;
    if (c >= B_ * D_) return;
    int b = c / D_, d = c % D_;
    const float* xp = x + (size_t)b * T_ * D_ + d;
    float* ip = g_integral + (size_t)b * T_ * D_ + d;
    float acc = xp[0];
    ip[0] = acc;
#pragma unroll 8
    for (int t = 1; t < T_; t++) {
        acc = fmaf(0.95f, acc, 0.05f * xp[(size_t)t * D_]);
        ip[(size_t)t * D_] = acc;
    }
}

// pack two fp32 into hi/lo bf16 pairs (4B stores)
__device__ __forceinline__ void split_store2(__nv_bfloat16* hi, __nv_bfloat16* lo,
                                             size_t idx, float v0, float v1) {
    __nv_bfloat16 h0 = __float2bfloat16(v0);
    __nv_bfloat16 h1 = __float2bfloat16(v1);
    __nv_bfloat16 l0 = __float2bfloat16(v0 - __bfloat162float(h0));
    __nv_bfloat16 l1 = __float2bfloat16(v1 - __bfloat162float(h1));
    __nv_bfloat162 hp; hp.x = h0; hp.y = h1;
    __nv_bfloat162 lp; lp.x = l0; lp.y = l1;
    *(__nv_bfloat162*)(hi + idx) = hp;
    *(__nv_bfloat162*)(lo + idx) = lp;
}

// pack 8 fp32 into hi/lo bf16 (16B stores)
__device__ __forceinline__ void split_store8(__nv_bfloat16* hi, __nv_bfloat16* lo,
                                             size_t idx, const float* v) {
    uint4 hq, lq;
    uint32_t* hw = (uint32_t*)&hq;
    uint32_t* lw = (uint32_t*)&lq;
#pragma unroll
    for (int j = 0; j < 4; j++) {
        __nv_bfloat16 h0 = __float2bfloat16(v[2 * j]);
        __nv_bfloat16 h1 = __float2bfloat16(v[2 * j + 1]);
        __nv_bfloat16 l0 = __float2bfloat16(v[2 * j] - __bfloat162float(h0));
        __nv_bfloat16 l1 = __float2bfloat16(v[2 * j + 1] - __bfloat162float(h1));
        __nv_bfloat162 hp; hp.x = h0; hp.y = h1;
        __nv_bfloat162 lp; lp.x = l0; lp.y = l1;
        hw[j] = *(uint32_t*)&hp;
        lw[j] = *(uint32_t*)&lp;
    }
    *(uint4*)(hi + idx) = hq;
    *(uint4*)(lo + idx) = lq;
}

__global__ void build_abc_kernel(const float* __restrict__ x,
                                 const float* __restrict__ kick_v)
{
    int r = blockIdx.x;
    int p = blockIdx.y;
    int t = r % T_;
    const float* par = g_params + (size_t)r * 12 + p * 4;
    float g0 = par[0], g1 = par[1], g2 = par[2], km = par[3];
    size_t base = ((size_t)p * NTOK + r) * K3;
    const float* xt = x + (size_t)r * D_;
    const float* integ = g_integral + (size_t)r * D_;
    for (int d8 = threadIdx.x; d8 < D_ / 8; d8 += blockDim.x) {
        int d = d8 * 8;
        float a[8], ii[8], dd[8];
#pragma unroll
        for (int j = 0; j < 8; j += 4) {
            float4 xv = *(const float4*)(xt + d + j);
            float4 iv = *(const float4*)(integ + d + j);
            float4 kv = *(const float4*)(kick_v + p * D_ + d + j);
            float4 pv = (t > 0) ? *(const float4*)(xt + d + j - D_)
                                : make_float4(xv.x, xv.y, xv.z, xv.w);
            a[j]   = g0 * xv.x; a[j+1] = g0 * xv.y; a[j+2] = g0 * xv.z; a[j+3] = g0 * xv.w;
            ii[j]  = g1 * iv.x; ii[j+1]= g1 * iv.y; ii[j+2]= g1 * iv.z; ii[j+3]= g1 * iv.w;
            dd[j]   = g2 * fmaf(km, kv.x, xv.x - pv.x);
            dd[j+1] = g2 * fmaf(km, kv.y, xv.y - pv.y);
            dd[j+2] = g2 * fmaf(km, kv.z, xv.z - pv.z);
            dd[j+3] = g2 * fmaf(km, kv.w, xv.w - pv.w);
        }
        split_store8(g_abc_hi, g_abc_lo, base + d,          a);
        split_store8(g_abc_hi, g_abc_lo, base + D_ + d,     ii);
        split_store8(g_abc_hi, g_abc_lo, base + 2 * D_ + d, dd);
    }
}

__global__ void conv_w_kernel(const float* __restrict__ Wp,
                              const float* __restrict__ Wi,
                              const float* __restrict__ Wd)
{
    size_t i8 = (size_t)blockIdx.x * blockDim.x + threadIdx.x;
    if (i8 >= (size_t)3 * 1024 * K3 / 8) return;
    size_t i = i8 * 8;
    int k = (int)(i % K3);
    size_t pn = i / K3;
    int sel = k >> 10;
    const float* src = (sel == 0) ? Wp : (sel == 1) ? Wi : Wd;
    const float* sp = src + pn * 1024 + (k & 1023);
    float v[8];
    *(float4*)v       = *(const float4*)sp;
    *(float4*)(v + 4) = *(const float4*)(sp + 4);
    split_store8(g_w_hi, g_w_lo, i, v);
}

__global__ void conv_ow_kernel(const float* __restrict__ ow)
{
    size_t i8 = (size_t)blockIdx.x * blockDim.x + threadIdx.x;
    if (i8 >= (size_t)1024 * 1024 / 8) return;
    size_t i = i8 * 8;
    float v[8];
    *(float4*)v       = *(const float4*)(ow + i);
    *(float4*)(v + 4) = *(const float4*)(ow + i + 4);
    split_store8(g_ow_hi, g_ow_lo, i, v);
}

// ============================ bf16x3 mma.sync GEMM v5 ============================
// C[M x 1024] = Ah*Bh^T + Al*Bh^T + Ah*Bl^T   (A [m][k], B=W [n][k], both k-contiguous)
// CTA tile 128(M) x 128(N), 8 warps 2x4 (warp tile 64x32), KT=64,
// 3-stage cp.async, 2 CTAs/SM (4 warps per SMSP for latency hiding).
#define KT      64
#define GSTG    3
#define ROWB    144                    // 128B data + 16B skew: conflict-free ldmatrix
#define ATILE_SZ (128 * ROWB)          // 18432
#define STAGE_SZ (2 * ATILE_SZ)        // 36864 (A + B, both 128 rows)
#define GEMM_SMEM (GSTG * STAGE_SZ)    // 110592 per CTA -> 2 CTAs = 221184/SM

__device__ __forceinline__ void gemm_issue(
    const __nv_bfloat16* As, const __nv_bfloat16* Bs, int K,
    uint32_t sb, int tid, int stage, int kk, int m0, int brow0)
{
    uint32_t st = sb + stage * STAGE_SZ;
#pragma unroll
    for (int j = 0; j < 8; j++) {
        int i = tid + j * 256;             // 0..2047
        bool isB = (i >= 1024);
        int idx = i & 1023;
        int row = idx >> 3, c = idx & 7;   // 8 x 16B = 128B per row
        const __nv_bfloat16* src = (isB ? Bs + (size_t)(brow0 + row) * K
                                        : As + (size_t)(m0 + row) * K) + kk + c * 8;
        uint32_t dst = st + (isB ? ATILE_SZ : 0) + row * ROWB + c * 16;
        cp_async16(dst, src);
    }
    cp_commit();
}

__global__ void __launch_bounds__(256, 2)
gemm_bf16x3(const __nv_bfloat16* __restrict__ Ah, const __nv_bfloat16* __restrict__ Al,
            const __nv_bfloat16* __restrict__ Bh, const __nv_bfloat16* __restrict__ Bl,
            float* c0, float* c1, float* c2, int kpt, int K)
{
    extern __shared__ __align__(256) char smem[];
    uint32_t sb = s2u(smem);
    int tid = threadIdx.x, lane = tid & 31, wid = tid >> 5;
    int wm = wid >> 2, wn = wid & 3;       // 2 x 4 warp grid, warp tile 64x32
    int by = blockIdx.y, bx = blockIdx.x;
    int proj = by >> 5;
    int m0 = by * 128;
    int brow0 = proj * 1024 + bx * 128;
    int NC = 3 * kpt;

    float d[4][4][4];                      // 4 m16-tiles x 4 n8-tiles
#pragma unroll
    for (int i = 0; i < 4; i++)
#pragma unroll
        for (int j = 0; j < 4; j++)
#pragma unroll
            for (int q = 0; q < 4; q++) d[i][j][q] = 0.f;

    uint32_t a_off = (uint32_t)((wm * 64 + (lane & 15)) * ROWB + (lane >> 4) * 16);
    uint32_t b_off = (uint32_t)(ATILE_SZ
                     + (wn * 32 + ((lane >> 4) << 3) + (lane & 7)) * ROWB
                     + ((lane >> 3) & 1) * 16);

    // producer counters (no division in the loop)
    int pterm = 0, pkc = 0;
    const __nv_bfloat16* pA = Ah;
    const __nv_bfloat16* pB = Bh;

    // prologue: 2 chunks (stages 0,1)
#pragma unroll
    for (int pr = 0; pr < 2; pr++) {
        gemm_issue(pA, pB, K, sb, tid, pr, pkc * KT, m0, brow0);
        if (++pkc == kpt) {
            pkc = 0; pterm++;
            pA = (pterm == 1) ? Al : Ah;
            pB = (pterm == 2) ? Bl : Bh;
        }
    }
    int pstage = 2;

    for (int kc = 0; kc < NC; kc++) {
        cp_wait1();
        __syncthreads();
        // issue chunk kc+2 into stage (kc+2)%3 = (kc-1)%3 (readers fenced by entry sync)
        if (pterm < 3) {
            gemm_issue(pA, pB, K, sb, tid, pstage, pkc * KT, m0, brow0);
            if (++pkc == kpt) {
                pkc = 0; pterm++;
                pA = (pterm == 1) ? Al : Ah;
                pB = (pterm == 2) ? Bl : Bh;
            }
            if (++pstage == GSTG) pstage = 0;
        } else {
            cp_commit();
        }

        uint32_t st = sb + (kc % GSTG) * STAGE_SZ;
#pragma unroll
        for (int ks = 0; ks < 4; ks++) {
            uint32_t a0 = st + a_off + ks * 32;
            uint32_t ab = st + b_off + ks * 32;
            uint32_t a[4][4];
#pragma unroll
            for (int mb = 0; mb < 4; mb++)
                ldsm_x4(a[mb], a0 + mb * 16 * ROWB);
            uint32_t b[2][4];
#pragma unroll
            for (int nb = 0; nb < 2; nb++)
                ldsm_x4(b[nb], ab + nb * 16 * ROWB);
#pragma unroll
            for (int mb = 0; mb < 4; mb++)
#pragma unroll
                for (int nb = 0; nb < 2; nb++) {
                    mma_bf16(d[mb][2 * nb],     a[mb], b[nb]);
                    mma_bf16(d[mb][2 * nb + 1], a[mb], b[nb] + 2);
                }
        }
    }

    // epilogue
    float* C = (proj == 0) ? c0 : (proj == 1) ? c1 : c2;
    int g = lane >> 2, q = lane & 3;
    int rb = (by & 31) * 128 + wm * 64;
    int cb = bx * 128 + wn * 32;
#pragma unroll
    for (int mb = 0; mb < 4; mb++) {
#pragma unroll
        for (int nt = 0; nt < 4; nt++) {
            float* cp = C + (size_t)(rb + mb * 16 + g) * 1024 + cb + nt * 8 + q * 2;
            *(float2*)cp = make_float2(d[mb][nt][0], d[mb][nt][1]);
            *(float2*)(cp + 8 * 1024) = make_float2(d[mb][nt][2], d[mb][nt][3]);
        }
    }
}

// ============================ sparse attention ============================
template<int AA>
__global__ void attn_kernel(const int* __restrict__ positions)
{
    int wid = (blockIdx.x * blockDim.x + threadIdx.x) >> 5;
    int lane = threadIdx.x & 31;
    if (wid >= B_ * H_ * T_) return;
    int t = wid % T_;
    int h = (wid / T_) % H_;
    int b = wid / (T_ * H_);

    const float* qp = g_q + ((size_t)b * T_ + t) * D_ + h * DH_;
    int d0 = lane * 2;
    float q0 = qp[d0], q1 = qp[d0 + 1];

    int nv = 1 + min(3, t);
    if (t >= 4) nv += (31 - __clz((unsigned)t)) - 1;

    float sc[AA];
    int ps[AA];
    float mx = -1e30f;
#pragma unroll
    for (int a = 0; a < AA; a++) {
        int pos = positions[t * AA + a];
        ps[a] = pos;
        const float* kp = g_k + ((size_t)b * T_ + pos) * D_ + h * DH_;
        float s = fmaf(q0, kp[d0], q1 * kp[d0 + 1]);
#pragma unroll
        for (int o = 16; o; o >>= 1) s += __shfl_xor_sync(0xffffffffu, s, o);
        s = (a < nv) ? s * 0.125f : -1e30f;
        sc[a] = s;
        mx = fmaxf(mx, s);
    }
    float sum = 0.f;
#pragma unroll
    for (int a = 0; a < AA; a++) { sc[a] = expf(sc[a] - mx); sum += sc[a]; }
    float inv = 1.f / sum;
    float o0 = 0.f, o1 = 0.f;
#pragma unroll
    for (int a = 0; a < AA; a++) {
        const float* vp = g_v + ((size_t)b * T_ + ps[a]) * D_ + h * DH_;
        float wgt = sc[a] * inv;
        o0 = fmaf(wgt, vp[d0], o0);
        o1 = fmaf(wgt, vp[d0 + 1], o1);
    }
    size_t oi = ((size_t)b * T_ + t) * D_ + h * DH_ + d0;
    split_store2(g_att_hi, g_att_lo, oi, o0, o1);
}

__global__ void attn_kernel_dyn(const int* __restrict__ positions, int A)
{
    int wid = (blockIdx.x * blockDim.x + threadIdx.x) >> 5;
    int lane = threadIdx.x & 31;
    if (wid >= B_ * H_ * T_) return;
    int t = wid % T_;
    int h = (wid / T_) % H_;
    int b = wid / (T_ * H_);
    const float* qp = g_q + ((size_t)b * T_ + t) * D_ + h * DH_;
    int d0 = lane * 2;
    float q0 = qp[d0], q1 = qp[d0 + 1];
    int nv = 1 + min(3, t);
    if (t >= 4) nv += (31 - __clz((unsigned)t)) - 1;
    float sc[32]; int ps[32];
    float mx = -1e30f;
    for (int a = 0; a < A; a++) {
        int pos = positions[t * A + a];
        ps[a] = pos;
        const float* kp = g_k + ((size_t)b * T_ + pos) * D_ + h * DH_;
        float s = fmaf(q0, kp[d0], q1 * kp[d0 + 1]);
        for (int o = 16; o; o >>= 1) s += __shfl_xor_sync(0xffffffffu, s, o);
        s = (a < nv) ? s * 0.125f : -1e30f;
        sc[a] = s; mx = fmaxf(mx, s);
    }
    float sum = 0.f;
    for (int a = 0; a < A; a++) { sc[a] = expf(sc[a] - mx); sum += sc[a]; }
    float inv = 1.f / sum;
    float o0 = 0.f, o1 = 0.f;
    for (int a = 0; a < A; a++) {
        const float* vp = g_v + ((size_t)b * T_ + ps[a]) * D_ + h * DH_;
        float wgt = sc[a] * inv;
        o0 = fmaf(wgt, vp[d0], o0);
        o1 = fmaf(wgt, vp[d0 + 1], o1);
    }
    size_t oi = ((size_t)b * T_ + t) * D_ + h * DH_ + d0;
    split_store2(g_att_hi, g_att_lo, oi, o0, o1);
}

// ============================ launcher ============================
extern "C" void kernel_launch(void* const* d_in, const int* in_sizes, int n_in,
                              void* d_out, int out_size)
{
    const float* x       = (const float*)d_in[0];
    const float* qkv_Wp  = (const float*)d_in[1];
    const float* qkv_Wi  = (const float*)d_in[2];
    const float* qkv_Wd  = (const float*)d_in[3];
    const float* gate_w  = (const float*)d_in[4];
    const float* gate_b  = (const float*)d_in[5];
    const float* kick_v  = (const float*)d_in[6];
    const float* kick_w  = (const float*)d_in[7];
    const float* kick_b  = (const float*)d_in[8];
    const float* o_w     = (const float*)d_in[9];
    const int*   positions = (const int*)d_in[10];
    int A = in_sizes[10] / T_;

    float* out = (float*)d_out;

    void *p_abc_hi, *p_abc_lo, *p_w_hi, *p_w_lo, *p_ow_hi, *p_ow_lo;
    void *p_q, *p_k, *p_v, *p_att_hi, *p_att_lo;
    cudaGetSymbolAddress(&p_abc_hi, g_abc_hi);
    cudaGetSymbolAddress(&p_abc_lo, g_abc_lo);
    cudaGetSymbolAddress(&p_w_hi, g_w_hi);
    cudaGetSymbolAddress(&p_w_lo, g_w_lo);
    cudaGetSymbolAddress(&p_ow_hi, g_ow_hi);
    cudaGetSymbolAddress(&p_ow_lo, g_ow_lo);
    cudaGetSymbolAddress(&p_q, g_q);
    cudaGetSymbolAddress(&p_k, g_k);
    cudaGetSymbolAddress(&p_v, g_v);
    cudaGetSymbolAddress(&p_att_hi, g_att_hi);
    cudaGetSymbolAddress(&p_att_lo, g_att_lo);

    cudaFuncSetAttribute(gemm_bf16x3, cudaFuncAttributeMaxDynamicSharedMemorySize, GEMM_SMEM);

    // 1. per-token gates / kick / stagnation
    token_stats_kernel<<<NTOK, 128>>>(x, gate_w, gate_b, kick_w, kick_b);
    // 2. EMA integral
    ema_kernel<<<(B_ * D_ + 255) / 256, 256>>>(x);
    // 3. weight hi/lo conversion (vectorized x8)
    conv_w_kernel<<<(3 * 1024 * K3 / 8 + 255) / 256, 256>>>(qkv_Wp, qkv_Wi, qkv_Wd);
    conv_ow_kernel<<<(1024 * 1024 / 8 + 255) / 256, 256>>>(o_w);
    // 4. gated GEMM inputs (hi/lo bf16)
    dim3 gb(NTOK, 3);
    build_abc_kernel<<<gb, 128>>>(x, kick_v);
    // 5. projection GEMMs: grid (1024/128, 3*4096/128) = (8, 96)
    dim3 pgrid(1024 / 128, 3 * (NTOK / 128));
    gemm_bf16x3<<<pgrid, 256, GEMM_SMEM>>>(
        (const __nv_bfloat16*)p_abc_hi, (const __nv_bfloat16*)p_abc_lo,
        (const __nv_bfloat16*)p_w_hi, (const __nv_bfloat16*)p_w_lo,
        (float*)p_q, (float*)p_k, (float*)p_v, K3 / KT, K3);
    // 6. sparse dilated attention
    int nwarps = B_ * H_ * T_;
    int nblocks = nwarps / 4;
    if (A == 15)
        attn_kernel<15><<<nblocks, 128>>>(positions);
    else
        attn_kernel_dyn<<<nblocks, 128>>>(positions, A);
    // 7. output projection: grid (8, 32)
    dim3 ogrid(1024 / 128, NTOK / 128);
    gemm_bf16x3<<<ogrid, 256, GEMM_SMEM>>>(
        (const __nv_bfloat16*)p_att_hi, (const __nv_bfloat16*)p_att_lo,
        (const __nv_bfloat16*)p_ow_hi, (const __nv_bfloat16*)p_ow_lo,
        out, out, out, D_ / KT, D_);
}

// round 8
// speedup vs baseline: 1.7237x; 1.6465x over previous
#include <cuda_runtime.h>
#include <math.h>
#include <stdint.h>

#define B_  2
#define T_  2048
#define D_  1024
#define H_  16
#define DH_ 64
#define NTOK (B_*T_)          // 4096
#define K3  3072

// ---------------- scratch (device globals; no allocation) ----------------
__device__ __align__(256) float g_integral[(size_t)NTOK * D_];
__device__ float g_params[(size_t)NTOK * 12];
// int8 dual-level quantized operands
__device__ __align__(256) int8_t g_a1[(size_t)3 * NTOK * K3];
__device__ __align__(256) int8_t g_a2[(size_t)3 * NTOK * K3];
__device__ __align__(256) int8_t g_w1[(size_t)3 * 1024 * K3];
__device__ __align__(256) int8_t g_w2[(size_t)3 * 1024 * K3];
__device__ __align__(256) int8_t g_o1[(size_t)NTOK * D_];
__device__ __align__(256) int8_t g_o2[(size_t)NTOK * D_];
__device__ __align__(256) int8_t g_ow1[(size_t)1024 * 1024];
__device__ __align__(256) int8_t g_ow2[(size_t)1024 * 1024];
// per-row scales
__device__ float g_sa[(size_t)3 * NTOK];
__device__ float g_sw[(size_t)3 * 1024];
__device__ float g_so[(size_t)NTOK];
__device__ float g_sow[(size_t)1024];
// fp32 intermediates
__device__ __align__(256) float g_q[(size_t)NTOK * D_];
__device__ __align__(256) float g_k[(size_t)NTOK * D_];
__device__ __align__(256) float g_v[(size_t)NTOK * D_];
__device__ __align__(256) float g_att[(size_t)NTOK * D_];

// ============================ PTX helpers (sm_100-baseline safe) ============================
__device__ __forceinline__ uint32_t s2u(const void* p) {
    uint32_t a;
    asm("{ .reg .u64 t; cvta.to.shared.u64 t, %1; cvt.u32.u64 %0, t; }" : "=r"(a) : "l"(p));
    return a;
}
__device__ __forceinline__ void cp_async16(uint32_t dst, const void* src) {
    asm volatile("cp.async.cg.shared.global [%0], [%1], 16;" :: "r"(dst), "l"(src));
}
__device__ __forceinline__ void cp_commit() {
    asm volatile("cp.async.commit_group;" ::: "memory");
}
__device__ __forceinline__ void cp_wait1() {
    asm volatile("cp.async.wait_group 1;" ::: "memory");
}
__device__ __forceinline__ void ldsm_x4(uint32_t* r, uint32_t addr) {
    asm volatile("ldmatrix.sync.aligned.m8n8.x4.shared.b16 {%0,%1,%2,%3}, [%4];"
        : "=r"(r[0]), "=r"(r[1]), "=r"(r[2]), "=r"(r[3]) : "r"(addr));
}
// int8 mma: m16n8k32, s32 accumulate
__device__ __forceinline__ void mma_s8(int* d, const uint32_t* a, const uint32_t* b) {
    asm volatile(
        "mma.sync.aligned.m16n8k32.row.col.s32.s8.s8.s32 "
        "{%0,%1,%2,%3}, {%4,%5,%6,%7}, {%8,%9}, {%0,%1,%2,%3};"
        : "+r"(d[0]), "+r"(d[1]), "+r"(d[2]), "+r"(d[3])
        : "r"(a[0]), "r"(a[1]), "r"(a[2]), "r"(a[3]), "r"(b[0]), "r"(b[1]));
}

// ============================ misc kernels ============================
__global__ void token_stats_kernel(const float* __restrict__ x,
                                   const float* __restrict__ gate_w,
                                   const float* __restrict__ gate_b,
                                   const float* __restrict__ kick_w,
                                   const float* __restrict__ kick_b)
{
    int r = blockIdx.x;
    int t = r % T_;
    const float* xt = x + (size_t)r * D_;
    int tid = threadIdx.x;

    float acc[15];
#pragma unroll
    for (int v = 0; v < 15; v++) acc[v] = 0.f;

    for (int d = tid; d < D_; d += 128) {
        float xv = xt[d];
        float pv = (t > 0) ? xt[d - D_] : 0.f;
        acc[0] = fmaf(xv, xv, acc[0]);
        acc[1] = fmaf(xv, pv, acc[1]);
        acc[2] = fmaf(pv, pv, acc[2]);
        acc[3] = fmaf(xv, kick_w[0 * D_ + d], acc[3]);
        acc[4] = fmaf(xv, kick_w[1 * D_ + d], acc[4]);
        acc[5] = fmaf(xv, kick_w[2 * D_ + d], acc[5]);
#pragma unroll
        for (int j = 0; j < 9; j++)
            acc[6 + j] = fmaf(xv, gate_w[j * D_ + d], acc[6 + j]);
    }
#pragma unroll
    for (int v = 0; v < 15; v++)
#pragma unroll
        for (int off = 16; off; off >>= 1)
            acc[v] += __shfl_down_sync(0xffffffffu, acc[v], off);

    __shared__ float red[15][4];
    int w = tid >> 5, l = tid & 31;
    if (l == 0)
#pragma unroll
        for (int v = 0; v < 15; v++) red[v][w] = acc[v];
    __syncthreads();

    if (tid == 0) {
        float s[15];
#pragma unroll
        for (int v = 0; v < 15; v++)
            s[v] = red[v][0] + red[v][1] + red[v][2] + red[v][3];
        float nt = fmaxf(sqrtf(s[0]), 1e-12f);
        float np = fmaxf(sqrtf(s[2]), 1e-12f);
        float cosv = (t > 0) ? s[1] / (nt * np) : 0.f;
        float stag = (cosv > 0.95f) ? 1.f : 0.f;
        float* out = g_params + (size_t)r * 12;
#pragma unroll
        for (int p = 0; p < 3; p++) {
            float ks = 1.f / (1.f + expf(-(s[3 + p] + kick_b[p])));
            float l0 = s[6 + p * 3 + 0] + gate_b[p * 3 + 0];
            float l1 = s[6 + p * 3 + 1] + gate_b[p * 3 + 1];
            float l2 = s[6 + p * 3 + 2] + gate_b[p * 3 + 2];
            float m = fmaxf(l0, fmaxf(l1, l2));
            float e0 = expf(l0 - m), e1 = expf(l1 - m), e2 = expf(l2 - m);
            float inv = 1.f / (e0 + e1 + e2);
            float g0 = fminf(e0 * inv, 0.6f);
            float g1 = fminf(e1 * inv, 0.6f);
            float g2 = fminf(e2 * inv, 0.6f);
            g1 = fmaxf(g1, 0.25f);
            float gi = 1.f / (g0 + g1 + g2);
            out[p * 4 + 0] = g0 * gi;
            out[p * 4 + 1] = g1 * gi;
            out[p * 4 + 2] = g2 * gi;
            out[p * 4 + 3] = stag * ks;
        }
    }
}

__global__ void ema_kernel(const float* __restrict__ x)
{
    int c = blockIdx.x * blockDim.x + threadIdx.x;
    if (c >= B_ * D_) return;
    int b = c / D_, d = c % D_;
    const float* xp = x + (size_t)b * T_ * D_ + d;
    float* ip = g_integral + (size_t)b * T_ * D_ + d;
    float acc = xp[0];
    ip[0] = acc;
#pragma unroll 8
    for (int t = 1; t < T_; t++) {
        acc = fmaf(0.95f, acc, 0.05f * xp[(size_t)t * D_]);
        ip[(size_t)t * D_] = acc;
    }
}

// ---------------- quantization helpers ----------------
__device__ __forceinline__ float block_max256(float mx) {
    __shared__ float red[8];
#pragma unroll
    for (int o = 16; o; o >>= 1)
        mx = fmaxf(mx, __shfl_xor_sync(0xffffffffu, mx, o));
    int w = threadIdx.x >> 5;
    if ((threadIdx.x & 31) == 0) red[w] = mx;
    __syncthreads();
    float m = fmaxf(fmaxf(red[0], red[1]), fmaxf(red[2], red[3]));
    m = fmaxf(m, fmaxf(fmaxf(red[4], red[5]), fmaxf(red[6], red[7])));
    return m;
}

__device__ __forceinline__ void quant2(float t, int8_t& q1, int8_t& q2) {
    int a1 = __float2int_rn(t);
    int a2 = __float2int_rn((t - (float)a1) * 256.f);
    a2 = max(-127, min(127, a2));
    q1 = (int8_t)a1;
    q2 = (int8_t)a2;
}

__device__ __forceinline__ void quant_store4(int8_t* d1, int8_t* d2, size_t idx,
                                             const float* v, float inv) {
    char4 c1, c2;
    quant2(v[0] * inv, (int8_t&)c1.x, (int8_t&)c2.x);
    quant2(v[1] * inv, (int8_t&)c1.y, (int8_t&)c2.y);
    quant2(v[2] * inv, (int8_t&)c1.z, (int8_t&)c2.z);
    quant2(v[3] * inv, (int8_t&)c1.w, (int8_t&)c2.w);
    *(char4*)(d1 + idx) = c1;
    *(char4*)(d2 + idx) = c2;
}

// build gated GEMM inputs, quantized: rows [g0*x | g1*integ | g2*deriv], K=3072
__global__ void build_abc_q(const float* __restrict__ x,
                            const float* __restrict__ kick_v)
{
    int r = blockIdx.x;
    int p = blockIdx.y;
    int t = r % T_;
    const float* par = g_params + (size_t)r * 12 + p * 4;
    float g0 = par[0], g1 = par[1], g2 = par[2], km = par[3];
    const float* xt = x + (size_t)r * D_;
    const float* integ = g_integral + (size_t)r * D_;
    int d = threadIdx.x * 4;

    float v[12];
    float4 xv = *(const float4*)(xt + d);
    float4 iv = *(const float4*)(integ + d);
    float4 kv = *(const float4*)(kick_v + p * D_ + d);
    float4 pv = (t > 0) ? *(const float4*)(xt + d - D_)
                        : make_float4(xv.x, xv.y, xv.z, xv.w);
    v[0] = g0 * xv.x; v[1] = g0 * xv.y; v[2] = g0 * xv.z; v[3] = g0 * xv.w;
    v[4] = g1 * iv.x; v[5] = g1 * iv.y; v[6] = g1 * iv.z; v[7] = g1 * iv.w;
    v[8]  = g2 * fmaf(km, kv.x, xv.x - pv.x);
    v[9]  = g2 * fmaf(km, kv.y, xv.y - pv.y);
    v[10] = g2 * fmaf(km, kv.z, xv.z - pv.z);
    v[11] = g2 * fmaf(km, kv.w, xv.w - pv.w);

    float mx = 0.f;
#pragma unroll
    for (int j = 0; j < 12; j++) mx = fmaxf(mx, fabsf(v[j]));
    mx = block_max256(mx);
    float inv = (mx > 0.f) ? 127.f / mx : 0.f;

    size_t base = ((size_t)p * NTOK + r) * K3;
    quant_store4(g_a1, g_a2, base + d,            v,     inv);
    quant_store4(g_a1, g_a2, base + D_ + d,       v + 4, inv);
    quant_store4(g_a1, g_a2, base + 2 * D_ + d,   v + 8, inv);
    if (threadIdx.x == 0) g_sa[(size_t)p * NTOK + r] = mx * (1.f / 127.f);
}

// quantize projection weights: row = (p, n), K=3072 = [Wp|Wi|Wd]
__global__ void conv_w_q(const float* __restrict__ Wp,
                         const float* __restrict__ Wi,
                         const float* __restrict__ Wd)
{
    int n = blockIdx.x;
    int p = blockIdx.y;
    int d = threadIdx.x * 4;
    size_t roff = ((size_t)p * 1024 + n) * 1024 + d;
    float v[12];
    *(float4*)(v)     = *(const float4*)(Wp + roff);
    *(float4*)(v + 4) = *(const float4*)(Wi + roff);
    *(float4*)(v + 8) = *(const float4*)(Wd + roff);

    float mx = 0.f;
#pragma unroll
    for (int j = 0; j < 12; j++) mx = fmaxf(mx, fabsf(v[j]));
    mx = block_max256(mx);
    float inv = (mx > 0.f) ? 127.f / mx : 0.f;

    size_t base = ((size_t)p * 1024 + n) * K3;
    quant_store4(g_w1, g_w2, base + d,            v,     inv);
    quant_store4(g_w1, g_w2, base + 1024 + d,     v + 4, inv);
    quant_store4(g_w1, g_w2, base + 2048 + d,     v + 8, inv);
    if (threadIdx.x == 0) g_sw[(size_t)p * 1024 + n] = mx * (1.f / 127.f);
}

// quantize a [rows x 1024] fp32 matrix per-row
__global__ void quant_rows_q(const float* __restrict__ src,
                             int8_t* __restrict__ d1, int8_t* __restrict__ d2,
                             float* __restrict__ sc)
{
    int r = blockIdx.x;
    int d = threadIdx.x * 4;
    float v[4];
    *(float4*)v = *(const float4*)(src + (size_t)r * 1024 + d);
    float mx = fmaxf(fmaxf(fabsf(v[0]), fabsf(v[1])), fmaxf(fabsf(v[2]), fabsf(v[3])));
    mx = block_max256(mx);
    float inv = (mx > 0.f) ? 127.f / mx : 0.f;
    quant_store4(d1, d2, (size_t)r * 1024 + d, v, inv);
    if (threadIdx.x == 0) sc[r] = mx * (1.f / 127.f);
}

// ============================ int8 dual-level mma GEMM ============================
// C[128x128 tile] = sA*sB*(A1*B1 + (A1*B2 + A2*B1)/256), int32 exact accumulation.
// A rows [m][k] int8 k-contig, B rows [n][k] int8 k-contig. KT=128 int8 (128B rows).
// 8 warps 2x4 (warp tile 64x32), 3-stage cp.async.
#define GSTG    3
#define ROWB    144                    // 128B data + 16B skew
#define ATILE   (128 * ROWB)           // 18432
#define STAGE_SZ (4 * ATILE)           // a1,a2,b1,b2 = 73728
#define GEMM_SMEM (GSTG * STAGE_SZ)    // 221184

__device__ __forceinline__ void issue_s8(
    const int8_t* A1, const int8_t* A2, const int8_t* B1, const int8_t* B2,
    int K, uint32_t su, int tid, int stage, int koff, int m0, int brow0)
{
    uint32_t st = su + stage * STAGE_SZ;
#pragma unroll
    for (int tile = 0; tile < 4; tile++) {
        const int8_t* srcb = (tile == 0) ? A1 : (tile == 1) ? A2 : (tile == 2) ? B1 : B2;
        int rbase = (tile < 2) ? m0 : brow0;
#pragma unroll
        for (int j = 0; j < 4; j++) {
            int idx = tid + j * 256;           // 0..1023
            int row = idx >> 3, c = idx & 7;
            cp_async16(st + tile * ATILE + row * ROWB + c * 16,
                       srcb + (size_t)(rbase + row) * K + koff + c * 16);
        }
    }
    cp_commit();
}

__global__ void __launch_bounds__(256, 1)
gemm_s8(const int8_t* __restrict__ A1, const int8_t* __restrict__ A2,
        const int8_t* __restrict__ B1, const int8_t* __restrict__ B2,
        const float* __restrict__ sa, const float* __restrict__ sbv,
        float* c0, float* c1, float* c2, int nchunks, int K)
{
    extern __shared__ __align__(256) char smem[];
    uint32_t su = s2u(smem);
    int tid = threadIdx.x, lane = tid & 31, wid = tid >> 5;
    int wm = wid >> 2, wn = wid & 3;       // 2 x 4, warp tile 64x32
    int by = blockIdx.y, bx = blockIdx.x;
    int proj = by >> 5;
    int m0 = by * 128;                     // A global row base
    int brow0 = proj * 1024 + bx * 128;    // B global row base

    int hi[4][4][4], mi[4][4][4];
#pragma unroll
    for (int i = 0; i < 4; i++)
#pragma unroll
        for (int j = 0; j < 4; j++)
#pragma unroll
            for (int q = 0; q < 4; q++) { hi[i][j][q] = 0; mi[i][j][q] = 0; }

    uint32_t a_off = (uint32_t)((wm * 64 + (lane & 15)) * ROWB + (lane >> 4) * 16);
    uint32_t b_off = (uint32_t)(2 * ATILE
                     + (wn * 32 + ((lane >> 4) << 3) + (lane & 7)) * ROWB
                     + ((lane >> 3) & 1) * 16);

    // prologue: chunks 0,1 -> stages 0,1
    issue_s8(A1, A2, B1, B2, K, su, tid, 0, 0, m0, brow0);
    issue_s8(A1, A2, B1, B2, K, su, tid, 1, 128, m0, brow0);

    for (int kc = 0; kc < nchunks; kc++) {
        cp_wait1();
        __syncthreads();
        // issue chunk kc+2 into stage (kc+2)%3 = (kc-1)%3 (readers fenced by entry sync)
        if (kc + 2 < nchunks)
            issue_s8(A1, A2, B1, B2, K, su, tid, (kc + 2) % GSTG, (kc + 2) * 128, m0, brow0);
        else
            cp_commit();

        uint32_t st = su + (kc % GSTG) * STAGE_SZ;
#pragma unroll
        for (int ks = 0; ks < 4; ks++) {       // 4 k32-slices of 32B
            uint32_t ao = st + a_off + ks * 32;
            uint32_t bo = st + b_off + ks * 32;
            uint32_t a1[4][4], a2[4][4];
#pragma unroll
            for (int mb = 0; mb < 4; mb++) {
                ldsm_x4(a1[mb], ao + mb * 16 * ROWB);
                ldsm_x4(a2[mb], ao + ATILE + mb * 16 * ROWB);
            }
            uint32_t b1[2][4], b2[2][4];
#pragma unroll
            for (int g2_ = 0; g2_ < 2; g2_++) {
                ldsm_x4(b1[g2_], bo + g2_ * 16 * ROWB);
                ldsm_x4(b2[g2_], bo + ATILE + g2_ * 16 * ROWB);
            }
#pragma unroll
            for (int mb = 0; mb < 4; mb++)
#pragma unroll
                for (int nb = 0; nb < 4; nb++) {
                    const uint32_t* bf1 = &b1[nb >> 1][(nb & 1) * 2];
                    const uint32_t* bf2 = &b2[nb >> 1][(nb & 1) * 2];
                    mma_s8(hi[mb][nb], a1[mb], bf1);
                    mma_s8(mi[mb][nb], a1[mb], bf2);
                    mma_s8(mi[mb][nb], a2[mb], bf1);
                }
        }
    }

    // epilogue: dequantize and store
    float* C = (proj == 0) ? c0 : (proj == 1) ? c1 : c2;
    int g = lane >> 2, q = lane & 3;
    int rb = (by & 31) * 128 + wm * 64;    // C row base (per-proj)
    int rowA = by * 128 + wm * 64;         // scale row base (global)
    int cb = bx * 128 + wn * 32;
#pragma unroll
    for (int mb = 0; mb < 4; mb++) {
        float sa0 = sa[rowA + mb * 16 + g];
        float sa1 = sa[rowA + mb * 16 + g + 8];
#pragma unroll
        for (int nt = 0; nt < 4; nt++) {
            int col = cb + nt * 8 + q * 2;
            float sb0 = sbv[proj * 1024 + col];
            float sb1 = sbv[proj * 1024 + col + 1];
            const int* h = hi[mb][nt];
            const int* m = mi[mb][nt];
            float f0 = sa0 * sb0 * ((float)h[0] + (float)m[0] * (1.f / 256.f));
            float f1 = sa0 * sb1 * ((float)h[1] + (float)m[1] * (1.f / 256.f));
            float f2 = sa1 * sb0 * ((float)h[2] + (float)m[2] * (1.f / 256.f));
            float f3 = sa1 * sb1 * ((float)h[3] + (float)m[3] * (1.f / 256.f));
            float* cp = C + (size_t)(rb + mb * 16 + g) * 1024 + col;
            *(float2*)cp = make_float2(f0, f1);
            *(float2*)(cp + 8 * 1024) = make_float2(f2, f3);
        }
    }
}

// ============================ sparse attention ============================
template<int AA>
__global__ void attn_kernel(const int* __restrict__ positions)
{
    int wid = (blockIdx.x * blockDim.x + threadIdx.x) >> 5;
    int lane = threadIdx.x & 31;
    if (wid >= B_ * H_ * T_) return;
    int t = wid % T_;
    int h = (wid / T_) % H_;
    int b = wid / (T_ * H_);

    const float* qp = g_q + ((size_t)b * T_ + t) * D_ + h * DH_;
    int d0 = lane * 2;
    float q0 = qp[d0], q1 = qp[d0 + 1];

    int nv = 1 + min(3, t);
    if (t >= 4) nv += (31 - __clz((unsigned)t)) - 1;

    float sc[AA];
    int ps[AA];
    float mx = -1e30f;
#pragma unroll
    for (int a = 0; a < AA; a++) {
        int pos = positions[t * AA + a];
        ps[a] = pos;
        const float* kp = g_k + ((size_t)b * T_ + pos) * D_ + h * DH_;
        float s = fmaf(q0, kp[d0], q1 * kp[d0 + 1]);
#pragma unroll
        for (int o = 16; o; o >>= 1) s += __shfl_xor_sync(0xffffffffu, s, o);
        s = (a < nv) ? s * 0.125f : -1e30f;
        sc[a] = s;
        mx = fmaxf(mx, s);
    }
    float sum = 0.f;
#pragma unroll
    for (int a = 0; a < AA; a++) { sc[a] = expf(sc[a] - mx); sum += sc[a]; }
    float inv = 1.f / sum;
    float o0 = 0.f, o1 = 0.f;
#pragma unroll
    for (int a = 0; a < AA; a++) {
        const float* vp = g_v + ((size_t)b * T_ + ps[a]) * D_ + h * DH_;
        float wgt = sc[a] * inv;
        o0 = fmaf(wgt, vp[d0], o0);
        o1 = fmaf(wgt, vp[d0 + 1], o1);
    }
    float* op = g_att + ((size_t)b * T_ + t) * D_ + h * DH_;
    *(float2*)(op + d0) = make_float2(o0, o1);
}

__global__ void attn_kernel_dyn(const int* __restrict__ positions, int A)
{
    int wid = (blockIdx.x * blockDim.x + threadIdx.x) >> 5;
    int lane = threadIdx.x & 31;
    if (wid >= B_ * H_ * T_) return;
    int t = wid % T_;
    int h = (wid / T_) % H_;
    int b = wid / (T_ * H_);
    const float* qp = g_q + ((size_t)b * T_ + t) * D_ + h * DH_;
    int d0 = lane * 2;
    float q0 = qp[d0], q1 = qp[d0 + 1];
    int nv = 1 + min(3, t);
    if (t >= 4) nv += (31 - __clz((unsigned)t)) - 1;
    float sc[32]; int ps[32];
    float mx = -1e30f;
    for (int a = 0; a < A; a++) {
        int pos = positions[t * A + a];
        ps[a] = pos;
        const float* kp = g_k + ((size_t)b * T_ + pos) * D_ + h * DH_;
        float s = fmaf(q0, kp[d0], q1 * kp[d0 + 1]);
        for (int o = 16; o; o >>= 1) s += __shfl_xor_sync(0xffffffffu, s, o);
        s = (a < nv) ? s * 0.125f : -1e30f;
        sc[a] = s; mx = fmaxf(mx, s);
    }
    float sum = 0.f;
    for (int a = 0; a < A; a++) { sc[a] = expf(sc[a] - mx); sum += sc[a]; }
    float inv = 1.f / sum;
    float o0 = 0.f, o1 = 0.f;
    for (int a = 0; a < A; a++) {
        const float* vp = g_v + ((size_t)b * T_ + ps[a]) * D_ + h * DH_;
        float wgt = sc[a] * inv;
        o0 = fmaf(wgt, vp[d0], o0);
        o1 = fmaf(wgt, vp[d0 + 1], o1);
    }
    float* op = g_att + ((size_t)b * T_ + t) * D_ + h * DH_;
    *(float2*)(op + d0) = make_float2(o0, o1);
}

// ============================ launcher ============================
extern "C" void kernel_launch(void* const* d_in, const int* in_sizes, int n_in,
                              void* d_out, int out_size)
{
    const float* x       = (const float*)d_in[0];
    const float* qkv_Wp  = (const float*)d_in[1];
    const float* qkv_Wi  = (const float*)d_in[2];
    const float* qkv_Wd  = (const float*)d_in[3];
    const float* gate_w  = (const float*)d_in[4];
    const float* gate_b  = (const float*)d_in[5];
    const float* kick_v  = (const float*)d_in[6];
    const float* kick_w  = (const float*)d_in[7];
    const float* kick_b  = (const float*)d_in[8];
    const float* o_w     = (const float*)d_in[9];
    const int*   positions = (const int*)d_in[10];
    int A = in_sizes[10] / T_;

    float* out = (float*)d_out;

    void *p_a1, *p_a2, *p_w1, *p_w2, *p_o1, *p_o2, *p_ow1, *p_ow2;
    void *p_sa, *p_sw, *p_so, *p_sow;
    void *p_q, *p_k, *p_v, *p_att;
    cudaGetSymbolAddress(&p_a1, g_a1);
    cudaGetSymbolAddress(&p_a2, g_a2);
    cudaGetSymbolAddress(&p_w1, g_w1);
    cudaGetSymbolAddress(&p_w2, g_w2);
    cudaGetSymbolAddress(&p_o1, g_o1);
    cudaGetSymbolAddress(&p_o2, g_o2);
    cudaGetSymbolAddress(&p_ow1, g_ow1);
    cudaGetSymbolAddress(&p_ow2, g_ow2);
    cudaGetSymbolAddress(&p_sa, g_sa);
    cudaGetSymbolAddress(&p_sw, g_sw);
    cudaGetSymbolAddress(&p_so, g_so);
    cudaGetSymbolAddress(&p_sow, g_sow);
    cudaGetSymbolAddress(&p_q, g_q);
    cudaGetSymbolAddress(&p_k, g_k);
    cudaGetSymbolAddress(&p_v, g_v);
    cudaGetSymbolAddress(&p_att, g_att);

    cudaFuncSetAttribute(gemm_s8, cudaFuncAttributeMaxDynamicSharedMemorySize, GEMM_SMEM);

    // 1. per-token gates / kick / stagnation
    token_stats_kernel<<<NTOK, 128>>>(x, gate_w, gate_b, kick_w, kick_b);
    // 2. EMA integral
    ema_kernel<<<(B_ * D_ + 255) / 256, 256>>>(x);
    // 3. quantize weights
    dim3 wg(1024, 3);
    conv_w_q<<<wg, 256>>>(qkv_Wp, qkv_Wi, qkv_Wd);
    quant_rows_q<<<1024, 256>>>(o_w, (int8_t*)p_ow1, (int8_t*)p_ow2, (float*)p_sow);
    // 4. build + quantize gated GEMM inputs
    dim3 gb(NTOK, 3);
    build_abc_q<<<gb, 256>>>(x, kick_v);
    // 5. projection GEMMs: grid (1024/128, 3*4096/128) = (8, 96)
    dim3 pgrid(8, 96);
    gemm_s8<<<pgrid, 256, GEMM_SMEM>>>(
        (const int8_t*)p_a1, (const int8_t*)p_a2,
        (const int8_t*)p_w1, (const int8_t*)p_w2,
        (const float*)p_sa, (const float*)p_sw,
        (float*)p_q, (float*)p_k, (float*)p_v, K3 / 128, K3);
    // 6. sparse dilated attention
    int nwarps = B_ * H_ * T_;
    int nblocks = nwarps / 4;
    if (A == 15)
        attn_kernel<15><<<nblocks, 128>>>(positions);
    else
        attn_kernel_dyn<<<nblocks, 128>>>(positions, A);
    // 7. quantize attention output, then output projection: grid (8, 32)
    quant_rows_q<<<NTOK, 256>>>((const float*)p_att, (int8_t*)p_o1, (int8_t*)p_o2, (float*)p_so);
    dim3 ogrid(8, 32);
    gemm_s8<<<ogrid, 256, GEMM_SMEM>>>(
        (const int8_t*)p_o1, (const int8_t*)p_o2,
        (const int8_t*)p_ow1, (const int8_t*)p_ow2,
        (const float*)p_so, (const float*)p_sow,
        out, out, out, D_ / 128, D_);
}